// round 15
// baseline (speedup 1.0000x reference)
#include <cuda_runtime.h>
#include <float.h>

#define N_COLS   32000
#define NV4      8000
#define THREADS  256
#define NWARPS   8
#define CHUNKF4  1024        // float4 per chunk (16 KB)
#define NCHUNK   8           // chunk 7 partial: f4 7168..7999 (832)
#define SEGW     176         // per-warp provisional float4-group capacity
#define SCALW    512         // per-warp scalar capacity (reuses buffer0)
#define MAX_ROWS 4096
#define SENT     (-1.0e30f)

__device__ float g_row_loss[MAX_ROWS];
__device__ unsigned g_done = 0;

__device__ __forceinline__ float max4(float4 v) {
    return fmaxf(fmaxf(v.x, v.y), fmaxf(v.z, v.w));
}
__device__ __forceinline__ void cpasync16(unsigned int saddr, const void* gaddr) {
    asm volatile("cp.async.cg.shared.global [%0], [%1], 16;" :: "r"(saddr), "l"(gaddr) : "memory");
}
__device__ __forceinline__ void cpasync_commit() {
    asm volatile("cp.async.commit_group;" ::: "memory");
}
template <int N>
__device__ __forceinline__ void cpasync_wait() {
    asm volatile("cp.async.wait_group %0;" :: "n"(N) : "memory");
}

// Issue chunk k into buf[k&1]; each thread copies only its own 4 float4
// columns, so no cross-thread hazard and no barrier is needed for reuse.
__device__ __forceinline__ void issue_chunk(unsigned int sbase, const float4* g4,
                                            int tid, int k) {
    unsigned int sb = sbase + (unsigned int)(((k & 1) * CHUNKF4 + tid) * 16);
    const float4* gp = g4 + k * CHUNKF4 + tid;
    cpasync16(sb,            gp);
    cpasync16(sb + 256 * 16, gp + 256);
    cpasync16(sb + 512 * 16, gp + 512);
    if (k < 7 || tid < 64) cpasync16(sb + 768 * 16, gp + 768);
    cpasync_commit();
}

__global__ void __launch_bounds__(THREADS)
entmax15_fused(const float* __restrict__ inp, const int* __restrict__ tgt,
               float* __restrict__ out, int rows) {
    extern __shared__ char smemraw[];
    float4* buf = (float4*)smemraw;                          // 32 KB (2x16 KB)
    float4* seg = (float4*)(smemraw + 2 * CHUNKF4 * 16);     // 8*176*16 = 22 KB
    __shared__ float redm[NWARPS];        // monotone warp maxima (racy-read safe)
    __shared__ float redA[NWARPS], redB[NWARPS], redC[NWARPS];
    __shared__ int   scnt[NWARPS], scnt2[NWARPS];
    __shared__ int   s_last;
    __shared__ float sred[THREADS];

    const int row  = blockIdx.x;
    const int tid  = threadIdx.x;
    const int lane = tid & 31;
    const int w    = tid >> 5;
    const float* rp = inp + (size_t)row * N_COLS;
    const float4* g4 = (const float4*)rp;
    const unsigned lm = (1u << lane) - 1u;
    float4* segw = seg + w * SEGW;
    volatile float* vredm = (volatile float*)redm;

    float tgl = 0.0f;
    if (tid == 0) {
        int ti = tgt[row];
        ti = (ti < 0) ? 0 : ((ti >= N_COLS) ? N_COLS - 1 : ti);
        tgl = __ldg(rp + ti);
    }

    const unsigned int sbase = (unsigned int)__cvta_generic_to_shared(buf);
    issue_chunk(sbase, g4, tid, 0);
    issue_chunk(sbase, g4, tid, 1);

    float lmax = -FLT_MAX;
    float thr  = -FLT_MAX;
    int   wcnt = 0;

    // ---- Chunk 0: establish block threshold (one barrier) ----
    {
        cpasync_wait<1>();
        const float4* bb = buf + tid;
        float4 va = bb[0], vb = bb[256], vc = bb[512], vd = bb[768];
        issue_chunk(sbase, g4, tid, 2);

        float g0 = max4(va), g1 = max4(vb), g2 = max4(vc), g3 = max4(vd);
        lmax = fmaxf(fmaxf(g0, g1), fmaxf(g2, g3));
        float wm = lmax;
        #pragma unroll
        for (int o = 16; o; o >>= 1) wm = fmaxf(wm, __shfl_xor_sync(0xffffffffu, wm, o));
        if (lane == 0) redm[w] = wm;
        __syncthreads();   // all redm slots initialized; from here reads are racy-safe
        float bm = -FLT_MAX;
        #pragma unroll
        for (int q = 0; q < NWARPS; ++q) bm = fmaxf(bm, vredm[q]);
        thr = bm - 2.0f;   // every redm value <= m  =>  never rejects a true candidate

        float gm4[4] = {g0, g1, g2, g3};
        float4 vv[4] = {va, vb, vc, vd};
        #pragma unroll
        for (int g = 0; g < 4; ++g) {
            bool p = (gm4[g] >= thr);
            unsigned b = __ballot_sync(0xffffffffu, p);
            if (p) {
                int pos = wcnt + __popc(b & lm);
                if (pos < SEGW) segw[pos] = vv[g];
            }
            wcnt += __popc(b);
        }
    }

    // ---- Chunks 1..7: fully barrier-free ----
    #pragma unroll 1
    for (int k = 1; k < NCHUNK; ++k) {
        if (k < NCHUNK - 1) cpasync_wait<1>(); else cpasync_wait<0>();

        const float4* bb = buf + ((k & 1) * CHUNKF4) + tid;
        float4 va = bb[0], vb = bb[256], vc = bb[512];
        float4 vd = (k < 7 || tid < 64) ? bb[768] : make_float4(SENT, SENT, SENT, SENT);

        if (k < NCHUNK - 2) issue_chunk(sbase, g4, tid, k + 2);

        float g0 = max4(va), g1 = max4(vb), g2 = max4(vc), g3 = max4(vd);
        lmax = fmaxf(lmax, fmaxf(fmaxf(g0, g1), fmaxf(g2, g3)));

        float wm = lmax;
        #pragma unroll
        for (int o = 16; o; o >>= 1) wm = fmaxf(wm, __shfl_xor_sync(0xffffffffu, wm, o));
        if (lane == 0) vredm[w] = wm;          // monotone publish (no sync)
        float bm = thr + 2.0f;
        #pragma unroll
        for (int q = 0; q < NWARPS; ++q) bm = fmaxf(bm, vredm[q]);  // stale reads are lower bounds
        thr = bm - 2.0f;

        float gm4[4] = {g0, g1, g2, g3};
        float4 vv[4] = {va, vb, vc, vd};
        #pragma unroll
        for (int g = 0; g < 4; ++g) {
            bool p = (gm4[g] >= thr);
            unsigned b = __ballot_sync(0xffffffffu, p);
            if (p) {
                int pos = wcnt + __popc(b & lm);
                if (pos < SEGW) segw[pos] = vv[g];
            }
            wcnt += __popc(b);
        }
    }

    // ---- exact row max + overflow ----
    float wm = lmax;
    #pragma unroll
    for (int o = 16; o; o >>= 1) wm = fmaxf(wm, __shfl_xor_sync(0xffffffffu, wm, o));
    if (lane == 0) { redA[w] = wm; scnt[w] = wcnt; }
    __syncthreads();   // stream done in all warps => buffers reusable, redA/scnt visible
    float m = redA[0];
    int ovf = 0;
    #pragma unroll
    for (int q = 0; q < NWARPS; ++q) {
        m = fmaxf(m, redA[q]);
        ovf |= (scnt[q] > SEGW);
    }
    const float cthr = m - 2.0f;
    const float cm   = -0.5f * m;

    // ---- compact groups -> true scalars (v >= m-2) into buffer0 (now free) ----
    float* scal = (float*)buf + w * SCALW;
    int sc = 0;
    const int myc = (wcnt < SEGW) ? wcnt : SEGW;
    for (int j = 0; j < myc; j += 32) {
        int idx = j + lane;
        bool valid = (idx < myc);
        float4 q = valid ? segw[idx] : make_float4(SENT, SENT, SENT, SENT);
        float xe[4] = {q.x, q.y, q.z, q.w};
        #pragma unroll
        for (int e = 0; e < 4; ++e) {
            bool kp = (xe[e] >= cthr);
            unsigned b = __ballot_sync(0xffffffffu, kp);
            if (kp) {
                int pos = sc + __popc(b & lm);
                if (pos < SCALW) scal[pos] = xe[e];
            }
            sc += __popc(b);
        }
    }
    if (lane == 0) scnt2[w] = sc;
    __syncthreads();
    #pragma unroll
    for (int q = 0; q < NWARPS; ++q) ovf |= (scnt2[q] > SCALW);
    int scc = (sc < SCALW) ? sc : SCALW;

    if (!ovf) {
        float tau = -1.0f;

        // ---- Newton stage 1: 3 iters over full candidate list ----
        for (int it = 0; it < 3; ++it) {
            float ct = cm - tau;
            float s1 = 0.0f, s2 = 0.0f;
            for (int i = lane; i < scc; i += 32) {
                float d = fmaxf(fmaf(scal[i], 0.5f, ct), 0.0f);
                s1 += d; s2 = fmaf(d, d, s2);
            }
            #pragma unroll
            for (int o = 16; o; o >>= 1) {
                s1 += __shfl_xor_sync(0xffffffffu, s1, o);
                s2 += __shfl_xor_sync(0xffffffffu, s2, o);
            }
            if (lane == 0) { redA[w] = s1; redB[w] = s2; }
            __syncthreads();
            float S1 = 0.0f, S2 = 0.0f;
            #pragma unroll
            for (int q = 0; q < NWARPS; ++q) { S1 += redA[q]; S2 += redB[q]; }
            __syncthreads();
            tau += (S2 - 1.0f) / (2.0f * S1);   // convex f, monotone from below
        }

        // ---- compact to {X >= tau3}: dropped elements stay inert forever ----
        {
            int sc2 = 0;
            for (int j = 0; j < scc; j += 32) {
                int idx = j + lane;
                bool valid = (idx < scc);
                float v = valid ? scal[idx] : SENT;
                bool kp = valid && (fmaf(v, 0.5f, cm) >= tau);
                unsigned b = __ballot_sync(0xffffffffu, kp);   // also orders reads before writes
                if (kp) scal[sc2 + __popc(b & lm)] = v;        // pos <= idx always
                sc2 += __popc(b);
            }
            scc = sc2;
        }

        // ---- Newton stage 2: 9 iters over tiny list ----
        for (int it = 0; it < 9; ++it) {
            float ct = cm - tau;
            float s1 = 0.0f, s2 = 0.0f;
            for (int i = lane; i < scc; i += 32) {
                float d = fmaxf(fmaf(scal[i], 0.5f, ct), 0.0f);
                s1 += d; s2 = fmaf(d, d, s2);
            }
            #pragma unroll
            for (int o = 16; o; o >>= 1) {
                s1 += __shfl_xor_sync(0xffffffffu, s1, o);
                s2 += __shfl_xor_sync(0xffffffffu, s2, o);
            }
            if (lane == 0) { redA[w] = s1; redB[w] = s2; }
            __syncthreads();
            float S1 = 0.0f, S2 = 0.0f;
            #pragma unroll
            for (int q = 0; q < NWARPS; ++q) { S1 += redA[q]; S2 += redB[q]; }
            __syncthreads();
            tau += (S2 - 1.0f) / (2.0f * S1);
        }

        // ---- final sums on compacted list ----
        float sp = 0.0f, s15 = 0.0f, spx = 0.0f;
        for (int i = lane; i < scc; i += 32) {
            float x = fmaf(scal[i], 0.5f, cm);
            float d = fmaxf(x - tau, 0.0f);
            float p = d * d;
            sp += p; s15 = fmaf(p, d, s15); spx = fmaf(p, x, spx);
        }
        #pragma unroll
        for (int o = 16; o; o >>= 1) {
            sp  += __shfl_xor_sync(0xffffffffu, sp,  o);
            s15 += __shfl_xor_sync(0xffffffffu, s15, o);
            spx += __shfl_xor_sync(0xffffffffu, spx, o);
        }
        if (lane == 0) { redA[w] = sp; redB[w] = s15; redC[w] = spx; }
        __syncthreads();
        if (tid == 0) {
            float SP = 0, S15 = 0, SPX = 0;
            #pragma unroll
            for (int q = 0; q < NWARPS; ++q) { SP += redA[q]; S15 += redB[q]; SPX += redC[q]; }
            float omega = (1.0f - S15) * (4.0f / 3.0f);
            g_row_loss[row] = omega + 2.0f * SPX + m * SP - tgl;
        }
    } else {
        // ---- Fallback (vanishing probability): Newton over GMEM row ----
        float tau = -1.0f;
        for (int it = 0; it < 14; ++it) {
            float ct = cm - tau;
            float s1 = 0.0f, s2 = 0.0f;
            for (int q = tid; q < NV4; q += THREADS) {
                float4 v = g4[q];
                float x4[4] = {v.x, v.y, v.z, v.w};
                #pragma unroll
                for (int c = 0; c < 4; ++c) {
                    float d = fmaxf(fmaf(x4[c], 0.5f, ct), 0.0f);
                    s1 += d; s2 = fmaf(d, d, s2);
                }
            }
            #pragma unroll
            for (int o = 16; o; o >>= 1) {
                s1 += __shfl_xor_sync(0xffffffffu, s1, o);
                s2 += __shfl_xor_sync(0xffffffffu, s2, o);
            }
            if (lane == 0) { redA[w] = s1; redB[w] = s2; }
            __syncthreads();
            float S1 = 0.0f, S2 = 0.0f;
            #pragma unroll
            for (int q = 0; q < NWARPS; ++q) { S1 += redA[q]; S2 += redB[q]; }
            __syncthreads();
            tau += (S2 - 1.0f) / (2.0f * S1);
        }
        float sp = 0.0f, s15 = 0.0f, spx = 0.0f;
        for (int q = tid; q < NV4; q += THREADS) {
            float4 v = g4[q];
            float x4[4] = {v.x, v.y, v.z, v.w};
            #pragma unroll
            for (int c = 0; c < 4; ++c) {
                float x = fmaf(x4[c], 0.5f, cm);
                float d = fmaxf(x - tau, 0.0f);
                float p = d * d;
                sp += p; s15 = fmaf(p, d, s15); spx = fmaf(p, x, spx);
            }
        }
        #pragma unroll
        for (int o = 16; o; o >>= 1) {
            sp  += __shfl_xor_sync(0xffffffffu, sp,  o);
            s15 += __shfl_xor_sync(0xffffffffu, s15, o);
            spx += __shfl_xor_sync(0xffffffffu, spx, o);
        }
        if (lane == 0) { redA[w] = sp; redB[w] = s15; redC[w] = spx; }
        __syncthreads();
        if (tid == 0) {
            float SP = 0, S15 = 0, SPX = 0;
            #pragma unroll
            for (int q = 0; q < NWARPS; ++q) { SP += redA[q]; S15 += redB[q]; SPX += redC[q]; }
            float omega = (1.0f - S15) * (4.0f / 3.0f);
            g_row_loss[row] = omega + 2.0f * SPX + m * SP - tgl;
        }
    }

    // ---- Completion: last block computes the mean (deterministic order) ----
    if (tid == 0) {
        __threadfence();
        unsigned old = atomicAdd(&g_done, 1u);
        s_last = (old == (unsigned)gridDim.x - 1u);
    }
    __syncthreads();
    if (s_last) {
        __threadfence();
        float v = 0.0f;
        for (int i = tid; i < rows; i += THREADS) v += g_row_loss[i];
        sred[tid] = v;
        __syncthreads();
        #pragma unroll
        for (int st = THREADS / 2; st; st >>= 1) {
            if (tid < st) sred[tid] += sred[tid + st];
            __syncthreads();
        }
        if (tid == 0) {
            out[0] = sred[0] / (float)rows;
            g_done = 0;   // reset for next graph replay
        }
    }
}

extern "C" void kernel_launch(void* const* d_in, const int* in_sizes, int n_in,
                              void* d_out, int out_size) {
    const float* inp = (const float*)d_in[0];
    const int*   tgt = (const int*)d_in[1];
    float*       out = (float*)d_out;
    const int rows = in_sizes[1];  // 4096

    const int dyn = 2 * CHUNKF4 * 16 + NWARPS * SEGW * 16;   // 32 KB + 22 KB
    cudaFuncSetAttribute(entmax15_fused, cudaFuncAttributeMaxDynamicSharedMemorySize, dyn);
    entmax15_fused<<<rows, THREADS, dyn>>>(inp, tgt, out, rows);
}

// round 16
// speedup vs baseline: 1.4480x; 1.4480x over previous
#include <cuda_runtime.h>
#include <float.h>

#define N_COLS   32000
#define NV4      8000
#define THREADS  256
#define NWARPS   8
#define CHUNKF4  1024        // float4 per chunk (16 KB)
#define NCHUNK   8           // chunk 7 partial: f4 7168..7999 (832)
#define SCALW    1024        // per-warp scalar capacity (reuses both buffers)
#define NEWTON   12
#define MAX_ROWS 4096
#define SENT     (-1.0e30f)

__device__ float g_row_loss[MAX_ROWS];
__device__ unsigned g_done = 0;

__device__ __forceinline__ float max4(float4 v) {
    return fmaxf(fmaxf(v.x, v.y), fmaxf(v.z, v.w));
}
__device__ __forceinline__ void cpasync16(unsigned int saddr, const void* gaddr) {
    asm volatile("cp.async.cg.shared.global [%0], [%1], 16;" :: "r"(saddr), "l"(gaddr) : "memory");
}
__device__ __forceinline__ void cpasync_commit() {
    asm volatile("cp.async.commit_group;" ::: "memory");
}
template <int N>
__device__ __forceinline__ void cpasync_wait() {
    asm volatile("cp.async.wait_group %0;" :: "n"(N) : "memory");
}

// Issue chunk k into buf[k&1]; each thread copies only its own 4 float4
// columns, so buffer reuse needs no barrier (same-thread produce/consume).
__device__ __forceinline__ void issue_chunk(unsigned int sbase, const float4* g4,
                                            int tid, int k) {
    unsigned int sb = sbase + (unsigned int)(((k & 1) * CHUNKF4 + tid) * 16);
    const float4* gp = g4 + k * CHUNKF4 + tid;
    cpasync16(sb,            gp);
    cpasync16(sb + 256 * 16, gp + 256);
    cpasync16(sb + 512 * 16, gp + 512);
    if (k < 7 || tid < 64) cpasync16(sb + 768 * 16, gp + 768);
    cpasync_commit();
}

// Build 4 mask bits (bit base+0..3) for one float4 vs thr.
__device__ __forceinline__ void mask4(unsigned& mk, float4 v, float thr, int base) {
    mk |= (v.x >= thr) ? (1u << base)       : 0u;
    mk |= (v.y >= thr) ? (1u << (base + 1)) : 0u;
    mk |= (v.z >= thr) ? (1u << (base + 2)) : 0u;
    mk |= (v.w >= thr) ? (1u << (base + 3)) : 0u;
}

__global__ void __launch_bounds__(THREADS)
entmax15_fused(const float* __restrict__ inp, const int* __restrict__ tgt,
               float* __restrict__ out, int rows) {
    extern __shared__ char smemraw[];
    float4* buf = (float4*)smemraw;                 // 32 KB (2x16 KB), reused as segments
    __shared__ float redA[NWARPS], redB[NWARPS], redC[NWARPS];
    __shared__ int   scnt[NWARPS];
    __shared__ int   s_last;
    __shared__ float sred[THREADS];

    const int row  = blockIdx.x;
    const int tid  = threadIdx.x;
    const int lane = tid & 31;
    const int w    = tid >> 5;
    const float* rp = inp + (size_t)row * N_COLS;
    const float4* g4 = (const float4*)rp;

    float tgl = 0.0f;
    if (tid == 0) {
        int ti = tgt[row];
        ti = (ti < 0) ? 0 : ((ti >= N_COLS) ? N_COLS - 1 : ti);
        tgl = __ldg(rp + ti);
    }

    const unsigned int sbase = (unsigned int)__cvta_generic_to_shared(buf);
    issue_chunk(sbase, g4, tid, 0);
    issue_chunk(sbase, g4, tid, 1);

    float lmax = -FLT_MAX;
    float thr;
    unsigned mk[NCHUNK];
    #pragma unroll
    for (int k = 0; k < NCHUNK; ++k) mk[k] = 0u;

    // ---- Chunk 0: establish block threshold (the only streaming barrier) ----
    {
        cpasync_wait<1>();
        const float4* bb = buf + tid;
        float4 va = bb[0], vb = bb[256], vc = bb[512], vd = bb[768];
        issue_chunk(sbase, g4, tid, 2);

        lmax = fmaxf(fmaxf(max4(va), max4(vb)), fmaxf(max4(vc), max4(vd)));
        float wm = lmax;
        #pragma unroll
        for (int o = 16; o; o >>= 1) wm = fmaxf(wm, __shfl_xor_sync(0xffffffffu, wm, o));
        if (lane == 0) redA[w] = wm;
        __syncthreads();
        float m0 = redA[0];
        #pragma unroll
        for (int q = 1; q < NWARPS; ++q) m0 = fmaxf(m0, redA[q]);
        __syncthreads();
        thr = m0 - 2.0f;   // m0 <= m  =>  never rejects a true candidate

        mask4(mk[0], va, thr, 0);
        mask4(mk[0], vb, thr, 4);
        mask4(mk[0], vc, thr, 8);
        mask4(mk[0], vd, thr, 12);
    }

    // ---- Chunks 1..7: barrier-free; mask-only consumer ----
    #pragma unroll 1
    for (int k = 1; k < NCHUNK; ++k) {
        if (k < NCHUNK - 1) cpasync_wait<1>(); else cpasync_wait<0>();

        const float4* bb = buf + ((k & 1) * CHUNKF4) + tid;
        float4 va = bb[0], vb = bb[256], vc = bb[512];
        float4 vd = (k < 7 || tid < 64) ? bb[768] : make_float4(SENT, SENT, SENT, SENT);

        if (k < NCHUNK - 2) issue_chunk(sbase, g4, tid, k + 2);

        lmax = fmaxf(lmax, fmaxf(fmaxf(max4(va), max4(vb)), fmaxf(max4(vc), max4(vd))));
        float wm = lmax;   // warp running max: lower bound of m -> safe filter
        #pragma unroll
        for (int o = 16; o; o >>= 1) wm = fmaxf(wm, __shfl_xor_sync(0xffffffffu, wm, o));
        thr = fmaxf(thr, wm - 2.0f);

        unsigned mkk = 0u;
        mask4(mkk, va, thr, 0);
        mask4(mkk, vb, thr, 4);
        mask4(mkk, vc, thr, 8);
        mask4(mkk, vd, thr, 12);   // vd sentinel for k==7,tid>=64 -> bits stay 0
        mk[k] = mkk;
    }

    // ---- exact row max + loose-candidate counts ----
    float wm2 = lmax;
    #pragma unroll
    for (int o = 16; o; o >>= 1) wm2 = fmaxf(wm2, __shfl_xor_sync(0xffffffffu, wm2, o));
    int pc = 0;
    #pragma unroll
    for (int k = 0; k < NCHUNK; ++k) pc += __popc(mk[k]);
    int ws = pc;
    #pragma unroll
    for (int o = 1; o < 32; o <<= 1) {
        int t = __shfl_up_sync(0xffffffffu, ws, o);
        if (lane >= o) ws += t;
    }
    if (lane == 0) redA[w] = wm2;
    if (lane == 31) scnt[w] = ws;    // warp total loose count
    __syncthreads();   // streaming done everywhere => buffers free; redA/scnt visible
    float m = redA[0];
    int ovf = 0;
    #pragma unroll
    for (int q = 0; q < NWARPS; ++q) {
        m = fmaxf(m, redA[q]);
        ovf |= (scnt[q] > SCALW);
    }
    const float cm = -0.5f * m;
    const int wtot = scnt[w];

    // ---- extraction: re-fetch masked elements (L2-hot, sparse) into warp segment ----
    float* scal = (float*)buf + w * SCALW;   // both buffers reused: 8 x 1024 floats
    if (!ovf) {
        int pos = ws - pc;                   // deterministic exclusive position
        #pragma unroll
        for (int k = 0; k < NCHUNK; ++k) {
            unsigned mm = mk[k];
            while (mm) {
                int b = __ffs(mm) - 1;
                mm &= mm - 1u;
                int q = b >> 2, c = b & 3;
                int fidx = ((k * CHUNKF4 + q * 256 + tid) << 2) + c;
                scal[pos++] = __ldg(rp + fidx);
            }
        }
    }
    __syncwarp();   // segment is warp-private; warp-level sync suffices

    if (!ovf) {
        // ---- block Newton over loose scalars (extras < m-2 are inert) ----
        float tau = -1.0f;
        for (int it = 0; it < NEWTON; ++it) {
            float ct = cm - tau;
            float s1 = 0.0f, s2 = 0.0f;
            for (int i = lane; i < wtot; i += 32) {
                float d = fmaxf(fmaf(scal[i], 0.5f, ct), 0.0f);
                s1 += d; s2 = fmaf(d, d, s2);
            }
            #pragma unroll
            for (int o = 16; o; o >>= 1) {
                s1 += __shfl_xor_sync(0xffffffffu, s1, o);
                s2 += __shfl_xor_sync(0xffffffffu, s2, o);
            }
            if (lane == 0) { redA[w] = s1; redB[w] = s2; }
            __syncthreads();
            float S1 = 0.0f, S2 = 0.0f;
            #pragma unroll
            for (int q = 0; q < NWARPS; ++q) { S1 += redA[q]; S2 += redB[q]; }
            __syncthreads();
            tau += (S2 - 1.0f) / (2.0f * S1);   // convex f, monotone from below
        }

        float sp = 0.0f, s15 = 0.0f, spx = 0.0f;
        for (int i = lane; i < wtot; i += 32) {
            float x = fmaf(scal[i], 0.5f, cm);
            float d = fmaxf(x - tau, 0.0f);
            float p = d * d;
            sp += p; s15 = fmaf(p, d, s15); spx = fmaf(p, x, spx);
        }
        #pragma unroll
        for (int o = 16; o; o >>= 1) {
            sp  += __shfl_xor_sync(0xffffffffu, sp,  o);
            s15 += __shfl_xor_sync(0xffffffffu, s15, o);
            spx += __shfl_xor_sync(0xffffffffu, spx, o);
        }
        if (lane == 0) { redA[w] = sp; redB[w] = s15; redC[w] = spx; }
        __syncthreads();
        if (tid == 0) {
            float SP = 0, S15 = 0, SPX = 0;
            #pragma unroll
            for (int q = 0; q < NWARPS; ++q) { SP += redA[q]; S15 += redB[q]; SPX += redC[q]; }
            float omega = (1.0f - S15) * (4.0f / 3.0f);
            g_row_loss[row] = omega + 2.0f * SPX + m * SP - tgl;
        }
    } else {
        // ---- Fallback (tail rows only): Newton over GMEM row ----
        float tau = -1.0f;
        for (int it = 0; it < 14; ++it) {
            float ct = cm - tau;
            float s1 = 0.0f, s2 = 0.0f;
            for (int q = tid; q < NV4; q += THREADS) {
                float4 v = g4[q];
                float x4[4] = {v.x, v.y, v.z, v.w};
                #pragma unroll
                for (int c = 0; c < 4; ++c) {
                    float d = fmaxf(fmaf(x4[c], 0.5f, ct), 0.0f);
                    s1 += d; s2 = fmaf(d, d, s2);
                }
            }
            #pragma unroll
            for (int o = 16; o; o >>= 1) {
                s1 += __shfl_xor_sync(0xffffffffu, s1, o);
                s2 += __shfl_xor_sync(0xffffffffu, s2, o);
            }
            if (lane == 0) { redA[w] = s1; redB[w] = s2; }
            __syncthreads();
            float S1 = 0.0f, S2 = 0.0f;
            #pragma unroll
            for (int q = 0; q < NWARPS; ++q) { S1 += redA[q]; S2 += redB[q]; }
            __syncthreads();
            tau += (S2 - 1.0f) / (2.0f * S1);
        }
        float sp = 0.0f, s15 = 0.0f, spx = 0.0f;
        for (int q = tid; q < NV4; q += THREADS) {
            float4 v = g4[q];
            float x4[4] = {v.x, v.y, v.z, v.w};
            #pragma unroll
            for (int c = 0; c < 4; ++c) {
                float x = fmaf(x4[c], 0.5f, cm);
                float d = fmaxf(x - tau, 0.0f);
                float p = d * d;
                sp += p; s15 = fmaf(p, d, s15); spx = fmaf(p, x, spx);
            }
        }
        #pragma unroll
        for (int o = 16; o; o >>= 1) {
            sp  += __shfl_xor_sync(0xffffffffu, sp,  o);
            s15 += __shfl_xor_sync(0xffffffffu, s15, o);
            spx += __shfl_xor_sync(0xffffffffu, spx, o);
        }
        if (lane == 0) { redA[w] = sp; redB[w] = s15; redC[w] = spx; }
        __syncthreads();
        if (tid == 0) {
            float SP = 0, S15 = 0, SPX = 0;
            #pragma unroll
            for (int q = 0; q < NWARPS; ++q) { SP += redA[q]; S15 += redB[q]; SPX += redC[q]; }
            float omega = (1.0f - S15) * (4.0f / 3.0f);
            g_row_loss[row] = omega + 2.0f * SPX + m * SP - tgl;
        }
    }

    // ---- Completion: last block computes the mean (deterministic order) ----
    if (tid == 0) {
        __threadfence();
        unsigned old = atomicAdd(&g_done, 1u);
        s_last = (old == (unsigned)gridDim.x - 1u);
    }
    __syncthreads();
    if (s_last) {
        __threadfence();
        float v = 0.0f;
        for (int i = tid; i < rows; i += THREADS) v += g_row_loss[i];
        sred[tid] = v;
        __syncthreads();
        #pragma unroll
        for (int st = THREADS / 2; st; st >>= 1) {
            if (tid < st) sred[tid] += sred[tid + st];
            __syncthreads();
        }
        if (tid == 0) {
            out[0] = sred[0] / (float)rows;
            g_done = 0;   // reset for next graph replay
        }
    }
}

extern "C" void kernel_launch(void* const* d_in, const int* in_sizes, int n_in,
                              void* d_out, int out_size) {
    const float* inp = (const float*)d_in[0];
    const int*   tgt = (const int*)d_in[1];
    float*       out = (float*)d_out;
    const int rows = in_sizes[1];  // 4096

    const int dyn = 2 * CHUNKF4 * 16;   // 32 KB (buffers double as segments)
    cudaFuncSetAttribute(entmax15_fused, cudaFuncAttributeMaxDynamicSharedMemorySize, dyn);
    entmax15_fused<<<rows, THREADS, dyn>>>(inp, tgt, out, rows);
}

// round 17
// speedup vs baseline: 1.5361x; 1.0609x over previous
#include <cuda_runtime.h>
#include <float.h>

#define N_COLS   32000
#define NV4      8000
#define THREADS  256
#define NWARPS   8
#define CHUNKF4  1024        // float4 per chunk (16 KB)
#define NCHUNK   8           // chunk 7 partial: f4 7168..7999 (832)
#define SCAP     32          // per-thread true-survivor slots (reuses buffers)
#define NEWTON   12
#define MAX_ROWS 4096
#define SENT     (-1.0e30f)

__device__ float g_row_loss[MAX_ROWS];
__device__ unsigned g_done = 0;

__device__ __forceinline__ float max4(float4 v) {
    return fmaxf(fmaxf(v.x, v.y), fmaxf(v.z, v.w));
}
__device__ __forceinline__ void cpasync16(unsigned int saddr, const void* gaddr) {
    asm volatile("cp.async.cg.shared.global [%0], [%1], 16;" :: "r"(saddr), "l"(gaddr) : "memory");
}
__device__ __forceinline__ void cpasync_commit() {
    asm volatile("cp.async.commit_group;" ::: "memory");
}
template <int N>
__device__ __forceinline__ void cpasync_wait() {
    asm volatile("cp.async.wait_group %0;" :: "n"(N) : "memory");
}

// Issue chunk k into buf[k&1]; each thread copies only its own 4 float4
// columns, so buffer reuse needs no barrier (same-thread produce/consume).
__device__ __forceinline__ void issue_chunk(unsigned int sbase, const float4* g4,
                                            int tid, int k) {
    unsigned int sb = sbase + (unsigned int)(((k & 1) * CHUNKF4 + tid) * 16);
    const float4* gp = g4 + k * CHUNKF4 + tid;
    cpasync16(sb,            gp);
    cpasync16(sb + 256 * 16, gp + 256);
    cpasync16(sb + 512 * 16, gp + 512);
    if (k < 7 || tid < 64) cpasync16(sb + 768 * 16, gp + 768);
    cpasync_commit();
}

__global__ void __launch_bounds__(THREADS)
entmax15_fused(const float* __restrict__ inp, const int* __restrict__ tgt,
               float* __restrict__ out, int rows) {
    extern __shared__ char smemraw[];
    float4* buf = (float4*)smemraw;      // 32 KB (2x16 KB), reused as survivor stash
    __shared__ float redA[NWARPS], redB[NWARPS], redC[NWARPS];
    __shared__ int   scnt[NWARPS];
    __shared__ int   s_last;
    __shared__ float sred[THREADS];

    const int row  = blockIdx.x;
    const int tid  = threadIdx.x;
    const int lane = tid & 31;
    const int w    = tid >> 5;
    const float* rp = inp + (size_t)row * N_COLS;
    const float4* g4 = (const float4*)rp;

    float tgl = 0.0f;
    if (tid == 0) {
        int ti = tgt[row];
        ti = (ti < 0) ? 0 : ((ti >= N_COLS) ? N_COLS - 1 : ti);
        tgl = __ldg(rp + ti);
    }

    const unsigned int sbase = (unsigned int)__cvta_generic_to_shared(buf);
    issue_chunk(sbase, g4, tid, 0);
    issue_chunk(sbase, g4, tid, 1);

    float lmax = -FLT_MAX;
    float thr;
    unsigned gmask = 0u;     // bit k*4+g: group g of chunk k passed the loose filter

    // ---- Chunk 0: establish block threshold (the only streaming barrier) ----
    {
        cpasync_wait<1>();
        const float4* bb = buf + tid;
        float4 va = bb[0], vb = bb[256], vc = bb[512], vd = bb[768];
        issue_chunk(sbase, g4, tid, 2);

        float g0 = max4(va), g1 = max4(vb), g2 = max4(vc), g3 = max4(vd);
        lmax = fmaxf(fmaxf(g0, g1), fmaxf(g2, g3));
        float wm = lmax;
        #pragma unroll
        for (int o = 16; o; o >>= 1) wm = fmaxf(wm, __shfl_xor_sync(0xffffffffu, wm, o));
        if (lane == 0) redA[w] = wm;
        __syncthreads();
        float m0 = redA[0];
        #pragma unroll
        for (int q = 1; q < NWARPS; ++q) m0 = fmaxf(m0, redA[q]);
        __syncthreads();
        thr = m0 - 2.0f;   // m0 <= m  =>  never rejects a true candidate's group

        gmask |= (g0 >= thr) ? 1u : 0u;
        gmask |= (g1 >= thr) ? 2u : 0u;
        gmask |= (g2 >= thr) ? 4u : 0u;
        gmask |= (g3 >= thr) ? 8u : 0u;
    }

    // ---- Chunks 1..7: barrier-free; group-mask-only consumer ----
    #pragma unroll 1
    for (int k = 1; k < NCHUNK; ++k) {
        if (k < NCHUNK - 1) cpasync_wait<1>(); else cpasync_wait<0>();

        const float4* bb = buf + ((k & 1) * CHUNKF4) + tid;
        float4 va = bb[0], vb = bb[256], vc = bb[512];
        float4 vd = (k < 7 || tid < 64) ? bb[768] : make_float4(SENT, SENT, SENT, SENT);

        if (k < NCHUNK - 2) issue_chunk(sbase, g4, tid, k + 2);

        float g0 = max4(va), g1 = max4(vb), g2 = max4(vc), g3 = max4(vd);
        lmax = fmaxf(lmax, fmaxf(fmaxf(g0, g1), fmaxf(g2, g3)));

        float wm = lmax;   // warp running max: lower bound of m -> safe filter
        #pragma unroll
        for (int o = 16; o; o >>= 1) wm = fmaxf(wm, __shfl_xor_sync(0xffffffffu, wm, o));
        thr = fmaxf(thr, wm - 2.0f);

        unsigned b0 = (unsigned)(k * 4);
        gmask |= (g0 >= thr) ? (1u << b0)       : 0u;
        gmask |= (g1 >= thr) ? (1u << (b0 + 1)) : 0u;
        gmask |= (g2 >= thr) ? (1u << (b0 + 2)) : 0u;
        gmask |= (g3 >= thr) ? (1u << (b0 + 3)) : 0u;   // chunk7/g3 sentinel -> bit 0
    }

    // ---- exact row max ----
    float wm2 = lmax;
    #pragma unroll
    for (int o = 16; o; o >>= 1) wm2 = fmaxf(wm2, __shfl_xor_sync(0xffffffffu, wm2, o));
    if (lane == 0) redA[w] = wm2;
    __syncthreads();   // all warps past streaming => buffers free; redA visible
    float m = redA[0];
    #pragma unroll
    for (int q = 1; q < NWARPS; ++q) m = fmaxf(m, redA[q]);
    const float cthr = m - 2.0f;   // exact: v >= m-2  <=>  X >= -1
    const float cm   = -0.5f * m;

    // ---- extraction: re-fetch accepted groups (LDG.128, L2-hot), keep TRUE
    //      candidates in a per-thread column stash (buffers reused) ----
    float* stash = (float*)buf;    // stash[slot*256 + tid], SCAP slots = 32 KB
    int kc = 0;
    {
        unsigned mm = gmask;
        while (mm) {
            int b = __ffs(mm) - 1;
            mm &= mm - 1u;
            int k = b >> 2, g = b & 3;
            float4 v = g4[k * CHUNKF4 + g * 256 + tid];
            float xe[4] = {v.x, v.y, v.z, v.w};
            #pragma unroll
            for (int c = 0; c < 4; ++c) {
                bool kp = (xe[c] >= cthr);
                if (kp && kc < SCAP) stash[kc * THREADS + tid] = xe[c];
                kc += kp;
            }
        }
    }
    unsigned ob = __ballot_sync(0xffffffffu, kc > SCAP);
    if (lane == 0) scnt[w] = (ob != 0u);
    __syncthreads();
    int ovf = 0;
    #pragma unroll
    for (int q = 0; q < NWARPS; ++q) ovf |= scnt[q];
    const int kcl = (kc < SCAP) ? kc : SCAP;

    if (!ovf) {
        // ---- block Newton over true support (per-thread columns) ----
        float tau = -1.0f;
        for (int it = 0; it < NEWTON; ++it) {
            float ct = cm - tau;
            float s1 = 0.0f, s2 = 0.0f;
            for (int j = 0; j < kcl; ++j) {
                float d = fmaxf(fmaf(stash[j * THREADS + tid], 0.5f, ct), 0.0f);
                s1 += d; s2 = fmaf(d, d, s2);
            }
            #pragma unroll
            for (int o = 16; o; o >>= 1) {
                s1 += __shfl_xor_sync(0xffffffffu, s1, o);
                s2 += __shfl_xor_sync(0xffffffffu, s2, o);
            }
            if (lane == 0) { redA[w] = s1; redB[w] = s2; }
            __syncthreads();
            float S1 = 0.0f, S2 = 0.0f;
            #pragma unroll
            for (int q = 0; q < NWARPS; ++q) { S1 += redA[q]; S2 += redB[q]; }
            __syncthreads();
            tau += (S2 - 1.0f) / (2.0f * S1);   // convex f, monotone from below
        }

        float sp = 0.0f, s15 = 0.0f, spx = 0.0f;
        for (int j = 0; j < kcl; ++j) {
            float x = fmaf(stash[j * THREADS + tid], 0.5f, cm);
            float d = fmaxf(x - tau, 0.0f);
            float p = d * d;
            sp += p; s15 = fmaf(p, d, s15); spx = fmaf(p, x, spx);
        }
        #pragma unroll
        for (int o = 16; o; o >>= 1) {
            sp  += __shfl_xor_sync(0xffffffffu, sp,  o);
            s15 += __shfl_xor_sync(0xffffffffu, s15, o);
            spx += __shfl_xor_sync(0xffffffffu, spx, o);
        }
        if (lane == 0) { redA[w] = sp; redB[w] = s15; redC[w] = spx; }
        __syncthreads();
        if (tid == 0) {
            float SP = 0, S15 = 0, SPX = 0;
            #pragma unroll
            for (int q = 0; q < NWARPS; ++q) { SP += redA[q]; S15 += redB[q]; SPX += redC[q]; }
            float omega = (1.0f - S15) * (4.0f / 3.0f);
            g_row_loss[row] = omega + 2.0f * SPX + m * SP - tgl;
        }
    } else {
        // ---- Fallback (vanishing probability): Newton over GMEM row ----
        float tau = -1.0f;
        for (int it = 0; it < 14; ++it) {
            float ct = cm - tau;
            float s1 = 0.0f, s2 = 0.0f;
            for (int q = tid; q < NV4; q += THREADS) {
                float4 v = g4[q];
                float x4[4] = {v.x, v.y, v.z, v.w};
                #pragma unroll
                for (int c = 0; c < 4; ++c) {
                    float d = fmaxf(fmaf(x4[c], 0.5f, ct), 0.0f);
                    s1 += d; s2 = fmaf(d, d, s2);
                }
            }
            #pragma unroll
            for (int o = 16; o; o >>= 1) {
                s1 += __shfl_xor_sync(0xffffffffu, s1, o);
                s2 += __shfl_xor_sync(0xffffffffu, s2, o);
            }
            if (lane == 0) { redA[w] = s1; redB[w] = s2; }
            __syncthreads();
            float S1 = 0.0f, S2 = 0.0f;
            #pragma unroll
            for (int q = 0; q < NWARPS; ++q) { S1 += redA[q]; S2 += redB[q]; }
            __syncthreads();
            tau += (S2 - 1.0f) / (2.0f * S1);
        }
        float sp = 0.0f, s15 = 0.0f, spx = 0.0f;
        for (int q = tid; q < NV4; q += THREADS) {
            float4 v = g4[q];
            float x4[4] = {v.x, v.y, v.z, v.w};
            #pragma unroll
            for (int c = 0; c < 4; ++c) {
                float x = fmaf(x4[c], 0.5f, cm);
                float d = fmaxf(x - tau, 0.0f);
                float p = d * d;
                sp += p; s15 = fmaf(p, d, s15); spx = fmaf(p, x, spx);
            }
        }
        #pragma unroll
        for (int o = 16; o; o >>= 1) {
            sp  += __shfl_xor_sync(0xffffffffu, sp,  o);
            s15 += __shfl_xor_sync(0xffffffffu, s15, o);
            spx += __shfl_xor_sync(0xffffffffu, spx, o);
        }
        if (lane == 0) { redA[w] = sp; redB[w] = s15; redC[w] = spx; }
        __syncthreads();
        if (tid == 0) {
            float SP = 0, S15 = 0, SPX = 0;
            #pragma unroll
            for (int q = 0; q < NWARPS; ++q) { SP += redA[q]; S15 += redB[q]; SPX += redC[q]; }
            float omega = (1.0f - S15) * (4.0f / 3.0f);
            g_row_loss[row] = omega + 2.0f * SPX + m * SP - tgl;
        }
    }

    // ---- Completion: last block computes the mean (deterministic order) ----
    if (tid == 0) {
        __threadfence();
        unsigned old = atomicAdd(&g_done, 1u);
        s_last = (old == (unsigned)gridDim.x - 1u);
    }
    __syncthreads();
    if (s_last) {
        __threadfence();
        float v = 0.0f;
        for (int i = tid; i < rows; i += THREADS) v += g_row_loss[i];
        sred[tid] = v;
        __syncthreads();
        #pragma unroll
        for (int st = THREADS / 2; st; st >>= 1) {
            if (tid < st) sred[tid] += sred[tid + st];
            __syncthreads();
        }
        if (tid == 0) {
            out[0] = sred[0] / (float)rows;
            g_done = 0;   // reset for next graph replay
        }
    }
}

extern "C" void kernel_launch(void* const* d_in, const int* in_sizes, int n_in,
                              void* d_out, int out_size) {
    const float* inp = (const float*)d_in[0];
    const int*   tgt = (const int*)d_in[1];
    float*       out = (float*)d_out;
    const int rows = in_sizes[1];  // 4096

    const int dyn = 2 * CHUNKF4 * 16;   // 32 KB (buffers double as survivor stash)
    cudaFuncSetAttribute(entmax15_fused, cudaFuncAttributeMaxDynamicSharedMemorySize, dyn);
    entmax15_fused<<<rows, THREADS, dyn>>>(inp, tgt, out, rows);
}